// round 1
// baseline (speedup 1.0000x reference)
#include <cuda_runtime.h>
#include <math.h>

#define Bb   8
#define Hh   32
#define Ss   4096
#define HD   128
#define Dd   4096
#define KV   4097          // Ss + 1 new token
#define SSTR 4112          // padded score stride
#define CAND 3585          // KV - RECENT(512)
#define KEEP 516           // IMP_SIZE(4) + RECENT(512)
#define KC   256           // split-K chunk for projections

#define OFF_K   32768
#define OFF_V   (32768 + 16908288)
#define OFF_IMP (32768 + 2*16908288)

// ---------------- static scratch (no allocations allowed) ----------------
__device__ float g_q[Bb*Dd];
__device__ float g_k[Bb*Dd];
__device__ float g_v[Bb*Dd];
__device__ float g_scores[Bb*Hh*SSTR];
__device__ float g_m[Bb*Hh];
__device__ float g_il[Bb*Hh];      // 1/l
__device__ float g_ctx[Bb*Hh*HD];  // == Bb*Dd floats
__device__ float g_imp[Bb*KV];
__device__ int   g_topk[Bb*4];

// ---------------- 1. zero accumulators ----------------
__global__ void k_zero(float* out0) {
    int i = blockIdx.x*blockDim.x + threadIdx.x;
    if (i < Bb*Dd) { g_q[i]=0.f; g_k[i]=0.f; g_v[i]=0.f; g_ctx[i]=0.f; out0[i]=0.f; }
}

// ---------------- 2. QKV projection: out[b][j] = sum_i h[b][i]*W[i][j] ----------------
__global__ void k_proj(const float* __restrict__ hs,
                       const float* __restrict__ Wq,
                       const float* __restrict__ Wk,
                       const float* __restrict__ Wv) {
    __shared__ float h_sm[Bb*KC];
    int w = blockIdx.z;
    const float* W = (w==0) ? Wq : ((w==1) ? Wk : Wv);
    float* out     = (w==0) ? g_q : ((w==1) ? g_k : g_v);
    int i0 = blockIdx.y * KC;
    int j  = blockIdx.x * 512 + threadIdx.x * 4;

    for (int idx = threadIdx.x; idx < Bb*KC; idx += blockDim.x)
        h_sm[idx] = hs[(idx/KC)*Dd + i0 + (idx%KC)];
    __syncthreads();

    float4 acc[Bb];
    #pragma unroll
    for (int b=0;b<Bb;b++) acc[b] = make_float4(0.f,0.f,0.f,0.f);

    const float4* Wp = (const float4*)(W + (size_t)i0*Dd + j);
    #pragma unroll 2
    for (int ii=0; ii<KC; ii++) {
        float4 wv = Wp[(size_t)ii*(Dd/4)];
        #pragma unroll
        for (int b=0;b<Bb;b++) {
            float hv = h_sm[b*KC+ii];
            acc[b].x += hv*wv.x; acc[b].y += hv*wv.y;
            acc[b].z += hv*wv.z; acc[b].w += hv*wv.w;
        }
    }
    #pragma unroll
    for (int b=0;b<Bb;b++) {
        atomicAdd(&out[b*Dd+j  ], acc[b].x);
        atomicAdd(&out[b*Dd+j+1], acc[b].y);
        atomicAdd(&out[b*Dd+j+2], acc[b].z);
        atomicAdd(&out[b*Dd+j+3], acc[b].w);
    }
}

// ---------------- 3. RoPE (position S) + new-token score ----------------
__global__ void k_rope() {
    __shared__ float qs[HD], ks[HD], red[HD];
    int bh = blockIdx.x;
    int d  = threadIdx.x;
    int base = (bh/Hh)*Dd + (bh%Hh)*HD;
    qs[d] = g_q[base+d]; ks[d] = g_k[base+d];
    __syncthreads();
    int i = d & 63;
    double ang = 4096.0 * pow(10000.0, -(double)(2*i)/128.0);
    float c = (float)cos(ang), s = (float)sin(ang);
    float qr = (d<64) ? -qs[d+64] : qs[d-64];
    float kr = (d<64) ? -ks[d+64] : ks[d-64];
    float qn = qs[d]*c + qr*s;
    float kn = ks[d]*c + kr*s;
    g_q[base+d]=qn; g_k[base+d]=kn;
    red[d] = qn*kn;
    __syncthreads();
    for (int st=64; st>0; st>>=1) { if (d<st) red[d]+=red[d+st]; __syncthreads(); }
    if (d==0) g_scores[(size_t)bh*SSTR + Ss] = red[0] * 0.08838834764831845f;
}

// ---------------- 4. scores over past keys (512 MB stream) ----------------
__global__ void k_scores(const float* __restrict__ Kc) {
    int bh   = blockIdx.y;
    int warp = threadIdx.x >> 5, lane = threadIdx.x & 31;
    int s0   = blockIdx.x*1024 + warp*128;
    const float4* qp = (const float4*)(g_q + (bh/Hh)*Dd + (bh%Hh)*HD);
    float4 q4 = qp[lane];
    const float4* Kp = (const float4*)Kc + (size_t)bh*Ss*32;
    float* sc = g_scores + (size_t)bh*SSTR;
    const float scale = 0.08838834764831845f;
    for (int s = s0; s < s0+128; s += 4) {
        float4 k0 = Kp[(size_t)(s+0)*32 + lane];
        float4 k1 = Kp[(size_t)(s+1)*32 + lane];
        float4 k2 = Kp[(size_t)(s+2)*32 + lane];
        float4 k3 = Kp[(size_t)(s+3)*32 + lane];
        float d0 = q4.x*k0.x + q4.y*k0.y + q4.z*k0.z + q4.w*k0.w;
        float d1 = q4.x*k1.x + q4.y*k1.y + q4.z*k1.z + q4.w*k1.w;
        float d2 = q4.x*k2.x + q4.y*k2.y + q4.z*k2.z + q4.w*k2.w;
        float d3 = q4.x*k3.x + q4.y*k3.y + q4.z*k3.z + q4.w*k3.w;
        #pragma unroll
        for (int off=16; off; off>>=1) {
            d0 += __shfl_xor_sync(0xFFFFFFFFu, d0, off);
            d1 += __shfl_xor_sync(0xFFFFFFFFu, d1, off);
            d2 += __shfl_xor_sync(0xFFFFFFFFu, d2, off);
            d3 += __shfl_xor_sync(0xFFFFFFFFu, d3, off);
        }
        if (lane == 0) {
            sc[s  ] = d0*scale; sc[s+1] = d1*scale;
            sc[s+2] = d2*scale; sc[s+3] = d3*scale;
        }
    }
}

// ---------------- 5. per-(b,h) max + logsum ----------------
__global__ void k_ml() {
    int bh = blockIdx.x;
    const float* sc = g_scores + (size_t)bh*SSTR;
    __shared__ float red[128];
    float m = -1e30f;
    for (int s = threadIdx.x; s < KV; s += 128) m = fmaxf(m, sc[s]);
    red[threadIdx.x] = m; __syncthreads();
    for (int st=64; st; st>>=1) { if (threadIdx.x<st) red[threadIdx.x]=fmaxf(red[threadIdx.x],red[threadIdx.x+st]); __syncthreads(); }
    m = red[0]; __syncthreads();
    float l = 0.f;
    for (int s = threadIdx.x; s < KV; s += 128) l += expf(sc[s]-m);
    red[threadIdx.x] = l; __syncthreads();
    for (int st=64; st; st>>=1) { if (threadIdx.x<st) red[threadIdx.x]+=red[threadIdx.x+st]; __syncthreads(); }
    if (threadIdx.x==0) { g_m[bh]=m; g_il[bh]=1.0f/red[0]; }
}

// ---------------- 6. ctx = sum_s p[s]*V[s] (512 MB stream) ----------------
__global__ void k_ctx(const float* __restrict__ Vc) {
    int bh = blockIdx.y;
    int d  = threadIdx.x;
    int s0 = blockIdx.x*1024;
    __shared__ float p_sm[128];
    float m = g_m[bh], inv = g_il[bh];
    const float* sc = g_scores + (size_t)bh*SSTR;
    const float* Vp = Vc + (size_t)bh*Ss*HD;
    float acc = 0.f;
    for (int t=0; t<8; t++) {
        int sb = s0 + t*128;
        p_sm[d] = expf(sc[sb+d]-m)*inv;
        __syncthreads();
        const float* vrow = Vp + (size_t)sb*HD + d;
        #pragma unroll 8
        for (int j=0; j<128; j++)
            acc += p_sm[j] * vrow[(size_t)j*HD];
        __syncthreads();
    }
    if (blockIdx.x == 3) {   // the new token (index 4096)
        float p = expf(sc[Ss]-m)*inv;
        acc += p * g_v[(bh/Hh)*Dd + (bh%Hh)*HD + d];
    }
    atomicAdd(&g_ctx[bh*HD + d], acc);
}

// ---------------- 7. importance: mean over heads + prev ----------------
__global__ void k_imp(const float* __restrict__ prev) {
    int idx = blockIdx.x*256 + threadIdx.x;
    if (idx >= Bb*KV) return;
    int b = idx / KV, s = idx % KV;
    float v = 0.f;
    #pragma unroll 4
    for (int h=0; h<Hh; h++) {
        int bh = b*Hh + h;
        v += expf(g_scores[(size_t)bh*SSTR + s] - g_m[bh]) * g_il[bh];
    }
    v *= (1.0f/32.0f);
    if (s < Ss) v += prev[b*Ss + s];
    g_imp[idx] = v;
}

// ---------------- 8. per-batch top-4 over imp[:CAND] ----------------
__global__ void k_topk() {
    int b = blockIdx.x;
    const float* imp = g_imp + b*KV;
    float bv[4]; int bi[4];
    #pragma unroll
    for (int r=0;r<4;r++){ bv[r]=-1e30f; bi[r]=0x7FFFFFFF; }
    for (int s = threadIdx.x; s < CAND; s += 256) {
        float v = imp[s];
        #pragma unroll
        for (int r=0;r<4;r++) {
            if (v > bv[r] || (v == bv[r] && s < bi[r])) {
                for (int q=3;q>r;q--){ bv[q]=bv[q-1]; bi[q]=bi[q-1]; }
                bv[r]=v; bi[r]=s; break;
            }
        }
    }
    __shared__ float sv[1024];
    __shared__ int   si[1024];
    #pragma unroll
    for (int r=0;r<4;r++){ sv[threadIdx.x*4+r]=bv[r]; si[threadIdx.x*4+r]=bi[r]; }
    __syncthreads();
    if (threadIdx.x == 0) {
        float tv[4]; int ti[4];
        #pragma unroll
        for (int r=0;r<4;r++){ tv[r]=-1e30f; ti[r]=0x7FFFFFFF; }
        for (int e=0;e<1024;e++) {
            float v = sv[e]; int i = si[e];
            for (int r=0;r<4;r++) {
                if (v > tv[r] || (v == tv[r] && i < ti[r])) {
                    for (int q=3;q>r;q--){ tv[q]=tv[q-1]; ti[q]=ti[q-1]; }
                    tv[r]=v; ti[r]=i; break;
                }
            }
        }
        // sort indices ascending
        for (int a=0;a<4;a++) for (int c=a+1;c<4;c++)
            if (ti[c] < ti[a]) { int t=ti[a]; ti[a]=ti[c]; ti[c]=t; }
        for (int r=0;r<4;r++) g_topk[b*4+r] = ti[r];
    }
}

// ---------------- 9. output projection: attn_out = ctx @ Wo ----------------
__global__ void k_oproj(const float* __restrict__ Wo, float* __restrict__ out) {
    __shared__ float h_sm[Bb*KC];
    int i0 = blockIdx.y * KC;
    int j  = blockIdx.x * 512 + threadIdx.x * 4;
    for (int idx = threadIdx.x; idx < Bb*KC; idx += blockDim.x)
        h_sm[idx] = g_ctx[(idx/KC)*Dd + i0 + (idx%KC)];
    __syncthreads();
    float4 acc[Bb];
    #pragma unroll
    for (int b=0;b<Bb;b++) acc[b] = make_float4(0.f,0.f,0.f,0.f);
    const float4* Wp = (const float4*)(Wo + (size_t)i0*Dd + j);
    #pragma unroll 2
    for (int ii=0; ii<KC; ii++) {
        float4 wv = Wp[(size_t)ii*(Dd/4)];
        #pragma unroll
        for (int b=0;b<Bb;b++) {
            float hv = h_sm[b*KC+ii];
            acc[b].x += hv*wv.x; acc[b].y += hv*wv.y;
            acc[b].z += hv*wv.z; acc[b].w += hv*wv.w;
        }
    }
    #pragma unroll
    for (int b=0;b<Bb;b++) {
        atomicAdd(&out[b*Dd+j  ], acc[b].x);
        atomicAdd(&out[b*Dd+j+1], acc[b].y);
        atomicAdd(&out[b*Dd+j+2], acc[b].z);
        atomicAdd(&out[b*Dd+j+3], acc[b].w);
    }
}

// ---------------- 10. eviction gather of K/V ----------------
__global__ void k_gather(const float* __restrict__ Kc, const float* __restrict__ Vc,
                         float* __restrict__ out) {
    int j  = blockIdx.x;        // 0..515
    int bh = blockIdx.y;        // 0..255
    int b = bh >> 5, h = bh & 31;
    int d = threadIdx.x;
    int idx = (j < 4) ? g_topk[b*4+j] : (CAND + (j-4));
    float kv, vv;
    if (idx < Ss) {
        size_t off = ((size_t)bh*Ss + idx)*HD + d;
        kv = Kc[off]; vv = Vc[off];
    } else {
        int o = b*Dd + h*HD + d;
        kv = g_k[o]; vv = g_v[o];
    }
    size_t doff = ((size_t)bh*KEEP + j)*HD + d;
    out[OFF_K + doff] = kv;
    out[OFF_V + doff] = vv;
}

// ---------------- 11. imp_kept gather ----------------
__global__ void k_impkept(float* __restrict__ out) {
    int b = blockIdx.x;
    for (int j = threadIdx.x; j < KEEP; j += blockDim.x) {
        int idx = (j < 4) ? g_topk[b*4+j] : (CAND + (j-4));
        out[OFF_IMP + b*KEEP + j] = g_imp[b*KV + idx];
    }
}

// ---------------- launch ----------------
extern "C" void kernel_launch(void* const* d_in, const int* in_sizes, int n_in,
                              void* d_out, int out_size) {
    const float* hs   = (const float*)d_in[0];
    const float* pk   = (const float*)d_in[1];
    const float* pv   = (const float*)d_in[2];
    const float* Wq   = (const float*)d_in[3];
    const float* Wk   = (const float*)d_in[4];
    const float* Wv   = (const float*)d_in[5];
    const float* Wo   = (const float*)d_in[6];
    const float* prev = (const float*)d_in[7];
    float* out = (float*)d_out;

    k_zero   <<<(Bb*Dd + 255)/256, 256>>>(out);
    k_proj   <<<dim3(Dd/512, Dd/KC, 3), 128>>>(hs, Wq, Wk, Wv);
    k_rope   <<<Bb*Hh, HD>>>();
    k_scores <<<dim3(4, Bb*Hh), 256>>>(pk);
    k_ml     <<<Bb*Hh, 128>>>();
    k_ctx    <<<dim3(4, Bb*Hh), 128>>>(pv);
    k_imp    <<<(Bb*KV + 255)/256, 256>>>(prev);
    k_topk   <<<Bb, 256>>>();
    k_oproj  <<<dim3(Dd/512, Dd/KC), 128>>>(Wo, out);
    k_gather <<<dim3(KEEP, Bb*Hh), HD>>>(pk, pv, out);
    k_impkept<<<Bb, 256>>>(out);
}

// round 4
// speedup vs baseline: 1.3136x; 1.3136x over previous
#include <cuda_runtime.h>
#include <math.h>

#define Bb   8
#define Hh   32
#define Ss   4096
#define HD   128
#define Dd   4096
#define KV   4097          // Ss + 1 new token
#define SSTR 4112          // padded score stride
#define CAND 3585          // KV - RECENT(512)
#define KEEP 516           // IMP_SIZE(4) + RECENT(512)
#define KC   128           // split-K chunk for projections

#define OFF_K   32768
#define OFF_V   (32768 + 16908288)
#define OFF_IMP (32768 + 2*16908288)

// ---------------- static scratch (no allocations allowed) ----------------
__device__ float g_q[Bb*Dd];
__device__ float g_k[Bb*Dd];
__device__ float g_v[Bb*Dd];
__device__ float g_scores[Bb*Hh*SSTR];
__device__ float g_m[Bb*Hh];
__device__ float g_il[Bb*Hh];      // 1/l
__device__ float g_ctx[Bb*Hh*HD];  // == Bb*Dd floats
__device__ float g_imp[Bb*KV];
__device__ int   g_topk[Bb*4];

// ---------------- 1. zero accumulators ----------------
__global__ void k_zero(float* out0) {
    int i = blockIdx.x*blockDim.x + threadIdx.x;
    if (i < Bb*Dd) { g_q[i]=0.f; g_k[i]=0.f; g_v[i]=0.f; g_ctx[i]=0.f; out0[i]=0.f; }
}

// ---------------- 2. QKV projection: out[b][j] = sum_i h[b][i]*W[i][j] ----------------
__global__ void k_proj(const float* __restrict__ hs,
                       const float* __restrict__ Wq,
                       const float* __restrict__ Wk,
                       const float* __restrict__ Wv) {
    __shared__ float h_sm[Bb*KC];
    int w = blockIdx.z;
    const float* W = (w==0) ? Wq : ((w==1) ? Wk : Wv);
    float* out     = (w==0) ? g_q : ((w==1) ? g_k : g_v);
    int i0 = blockIdx.y * KC;
    int j  = blockIdx.x * 512 + threadIdx.x * 4;

    for (int idx = threadIdx.x; idx < Bb*KC; idx += blockDim.x)
        h_sm[idx] = hs[(idx/KC)*Dd + i0 + (idx%KC)];
    __syncthreads();

    float4 acc[Bb];
    #pragma unroll
    for (int b=0;b<Bb;b++) acc[b] = make_float4(0.f,0.f,0.f,0.f);

    const float4* Wp = (const float4*)(W + (size_t)i0*Dd + j);
    for (int ii=0; ii<KC; ii+=4) {
        float4 w0 = Wp[(size_t)(ii+0)*(Dd/4)];
        float4 w1 = Wp[(size_t)(ii+1)*(Dd/4)];
        float4 w2 = Wp[(size_t)(ii+2)*(Dd/4)];
        float4 w3 = Wp[(size_t)(ii+3)*(Dd/4)];
        #pragma unroll
        for (int b=0;b<Bb;b++) {
            float h0 = h_sm[b*KC+ii+0], h1 = h_sm[b*KC+ii+1];
            float h2 = h_sm[b*KC+ii+2], h3 = h_sm[b*KC+ii+3];
            acc[b].x += h0*w0.x + h1*w1.x + h2*w2.x + h3*w3.x;
            acc[b].y += h0*w0.y + h1*w1.y + h2*w2.y + h3*w3.y;
            acc[b].z += h0*w0.z + h1*w1.z + h2*w2.z + h3*w3.z;
            acc[b].w += h0*w0.w + h1*w1.w + h2*w2.w + h3*w3.w;
        }
    }
    #pragma unroll
    for (int b=0;b<Bb;b++) {
        atomicAdd(&out[b*Dd+j  ], acc[b].x);
        atomicAdd(&out[b*Dd+j+1], acc[b].y);
        atomicAdd(&out[b*Dd+j+2], acc[b].z);
        atomicAdd(&out[b*Dd+j+3], acc[b].w);
    }
}

// ---------------- 3. RoPE (position S) + new-token score ----------------
__global__ void k_rope() {
    __shared__ float qs[HD], ks[HD], red[HD];
    int bh = blockIdx.x;
    int d  = threadIdx.x;
    int base = (bh/Hh)*Dd + (bh%Hh)*HD;
    qs[d] = g_q[base+d]; ks[d] = g_k[base+d];
    __syncthreads();
    int i = d & 63;
    double ang = 4096.0 * pow(10000.0, -(double)(2*i)/128.0);
    float c = (float)cos(ang), s = (float)sin(ang);
    float qr = (d<64) ? -qs[d+64] : qs[d-64];
    float kr = (d<64) ? -ks[d+64] : ks[d-64];
    float qn = qs[d]*c + qr*s;
    float kn = ks[d]*c + kr*s;
    g_q[base+d]=qn; g_k[base+d]=kn;
    red[d] = qn*kn;
    __syncthreads();
    for (int st=64; st>0; st>>=1) { if (d<st) red[d]+=red[d+st]; __syncthreads(); }
    if (d==0) g_scores[(size_t)bh*SSTR + Ss] = red[0] * 0.08838834764831845f;
}

// ---------------- 4. scores over past keys (512 MB stream) ----------------
__global__ void k_scores(const float* __restrict__ Kc) {
    int bh   = blockIdx.y;
    int warp = threadIdx.x >> 5, lane = threadIdx.x & 31;
    int s0   = blockIdx.x*1024 + warp*128;
    const float4* qp = (const float4*)(g_q + (bh/Hh)*Dd + (bh%Hh)*HD);
    float4 q4 = qp[lane];
    const float4* Kp = (const float4*)Kc + (size_t)bh*Ss*32;
    float* sc = g_scores + (size_t)bh*SSTR;
    const float scale = 0.08838834764831845f;
    for (int s = s0; s < s0+128; s += 8) {
        float d0,d1,d2,d3,d4,d5,d6,d7;
        {
            float4 k0 = Kp[(size_t)(s+0)*32 + lane];
            float4 k1 = Kp[(size_t)(s+1)*32 + lane];
            float4 k2 = Kp[(size_t)(s+2)*32 + lane];
            float4 k3 = Kp[(size_t)(s+3)*32 + lane];
            float4 k4 = Kp[(size_t)(s+4)*32 + lane];
            float4 k5 = Kp[(size_t)(s+5)*32 + lane];
            float4 k6 = Kp[(size_t)(s+6)*32 + lane];
            float4 k7 = Kp[(size_t)(s+7)*32 + lane];
            d0 = q4.x*k0.x + q4.y*k0.y + q4.z*k0.z + q4.w*k0.w;
            d1 = q4.x*k1.x + q4.y*k1.y + q4.z*k1.z + q4.w*k1.w;
            d2 = q4.x*k2.x + q4.y*k2.y + q4.z*k2.z + q4.w*k2.w;
            d3 = q4.x*k3.x + q4.y*k3.y + q4.z*k3.z + q4.w*k3.w;
            d4 = q4.x*k4.x + q4.y*k4.y + q4.z*k4.z + q4.w*k4.w;
            d5 = q4.x*k5.x + q4.y*k5.y + q4.z*k5.z + q4.w*k5.w;
            d6 = q4.x*k6.x + q4.y*k6.y + q4.z*k6.z + q4.w*k6.w;
            d7 = q4.x*k7.x + q4.y*k7.y + q4.z*k7.z + q4.w*k7.w;
        }
        #pragma unroll
        for (int off=16; off; off>>=1) {
            d0 += __shfl_xor_sync(0xFFFFFFFFu, d0, off);
            d1 += __shfl_xor_sync(0xFFFFFFFFu, d1, off);
            d2 += __shfl_xor_sync(0xFFFFFFFFu, d2, off);
            d3 += __shfl_xor_sync(0xFFFFFFFFu, d3, off);
            d4 += __shfl_xor_sync(0xFFFFFFFFu, d4, off);
            d5 += __shfl_xor_sync(0xFFFFFFFFu, d5, off);
            d6 += __shfl_xor_sync(0xFFFFFFFFu, d6, off);
            d7 += __shfl_xor_sync(0xFFFFFFFFu, d7, off);
        }
        if (lane == 0) {
            sc[s  ] = d0*scale; sc[s+1] = d1*scale;
            sc[s+2] = d2*scale; sc[s+3] = d3*scale;
            sc[s+4] = d4*scale; sc[s+5] = d5*scale;
            sc[s+6] = d6*scale; sc[s+7] = d7*scale;
        }
    }
}

// ---------------- 5. per-(b,h) max + logsum ----------------
__global__ void k_ml() {
    int bh = blockIdx.x;
    const float* sc = g_scores + (size_t)bh*SSTR;
    __shared__ float red[128];
    float m = -1e30f;
    for (int s = threadIdx.x; s < KV; s += 128) m = fmaxf(m, sc[s]);
    red[threadIdx.x] = m; __syncthreads();
    for (int st=64; st; st>>=1) { if (threadIdx.x<st) red[threadIdx.x]=fmaxf(red[threadIdx.x],red[threadIdx.x+st]); __syncthreads(); }
    m = red[0]; __syncthreads();
    float l = 0.f;
    for (int s = threadIdx.x; s < KV; s += 128) l += expf(sc[s]-m);
    red[threadIdx.x] = l; __syncthreads();
    for (int st=64; st; st>>=1) { if (threadIdx.x<st) red[threadIdx.x]+=red[threadIdx.x+st]; __syncthreads(); }
    if (threadIdx.x==0) { g_m[bh]=m; g_il[bh]=1.0f/red[0]; }
}

// ---------------- 6. ctx = sum_s p[s]*V[s] (512 MB stream, warp-per-row f4) ----------------
__global__ void k_ctx(const float* __restrict__ Vc) {
    int bh   = blockIdx.y;
    int warp = threadIdx.x >> 5, lane = threadIdx.x & 31;
    int s0   = blockIdx.x*1024 + warp*128;
    float m = g_m[bh], inv = g_il[bh];
    const float* sc = g_scores + (size_t)bh*SSTR;
    const float4* Vp = (const float4*)Vc + (size_t)bh*Ss*32;
    float4 acc = make_float4(0.f,0.f,0.f,0.f);
    for (int s = s0; s < s0+128; s += 4) {
        float p0 = sc[s], p1 = sc[s+1], p2 = sc[s+2], p3 = sc[s+3];
        float4 v0 = Vp[(size_t)(s+0)*32 + lane];
        float4 v1 = Vp[(size_t)(s+1)*32 + lane];
        float4 v2 = Vp[(size_t)(s+2)*32 + lane];
        float4 v3 = Vp[(size_t)(s+3)*32 + lane];
        p0 = expf(p0-m)*inv; p1 = expf(p1-m)*inv;
        p2 = expf(p2-m)*inv; p3 = expf(p3-m)*inv;
        acc.x += p0*v0.x + p1*v1.x + p2*v2.x + p3*v3.x;
        acc.y += p0*v0.y + p1*v1.y + p2*v2.y + p3*v3.y;
        acc.z += p0*v0.z + p1*v1.z + p2*v2.z + p3*v3.z;
        acc.w += p0*v0.w + p1*v1.w + p2*v2.w + p3*v3.w;
    }
    __shared__ float sm[8*128];
    sm[warp*128 + lane*4+0] = acc.x;
    sm[warp*128 + lane*4+1] = acc.y;
    sm[warp*128 + lane*4+2] = acc.z;
    sm[warp*128 + lane*4+3] = acc.w;
    __syncthreads();
    if (threadIdx.x < 128) {
        int d = threadIdx.x;
        float a = 0.f;
        #pragma unroll
        for (int w=0; w<8; w++) a += sm[w*128 + d];
        if (blockIdx.x == 3) {   // the new token (index 4096)
            float p = expf(sc[Ss]-m)*inv;
            a += p * g_v[(bh/Hh)*Dd + (bh%Hh)*HD + d];
        }
        atomicAdd(&g_ctx[bh*HD + d], a);
    }
}

// ---------------- 7. importance: mean over heads + prev ----------------
__global__ void k_imp(const float* __restrict__ prev) {
    int idx = blockIdx.x*256 + threadIdx.x;
    if (idx >= Bb*KV) return;
    int b = idx / KV, s = idx % KV;
    float v = 0.f;
    #pragma unroll 4
    for (int h=0; h<Hh; h++) {
        int bh = b*Hh + h;
        v += expf(g_scores[(size_t)bh*SSTR + s] - g_m[bh]) * g_il[bh];
    }
    v *= (1.0f/32.0f);
    if (s < Ss) v += prev[b*Ss + s];
    g_imp[idx] = v;
}

// ---------------- 8. per-batch top-4 over imp[:CAND] ----------------
__global__ void k_topk() {
    int b = blockIdx.x;
    const float* imp = g_imp + b*KV;
    float bv[4]; int bi[4];
    #pragma unroll
    for (int r=0;r<4;r++){ bv[r]=-1e30f; bi[r]=0x7FFFFFFF; }
    for (int s = threadIdx.x; s < CAND; s += 256) {
        float v = imp[s];
        #pragma unroll
        for (int r=0;r<4;r++) {
            if (v > bv[r] || (v == bv[r] && s < bi[r])) {
                for (int q=3;q>r;q--){ bv[q]=bv[q-1]; bi[q]=bi[q-1]; }
                bv[r]=v; bi[r]=s; break;
            }
        }
    }
    __shared__ float sv[1024];
    __shared__ int   si[1024];
    #pragma unroll
    for (int r=0;r<4;r++){ sv[threadIdx.x*4+r]=bv[r]; si[threadIdx.x*4+r]=bi[r]; }
    __syncthreads();
    if (threadIdx.x == 0) {
        float tv[4]; int ti[4];
        #pragma unroll
        for (int r=0;r<4;r++){ tv[r]=-1e30f; ti[r]=0x7FFFFFFF; }
        for (int e=0;e<1024;e++) {
            float v = sv[e]; int i = si[e];
            for (int r=0;r<4;r++) {
                if (v > tv[r] || (v == tv[r] && i < ti[r])) {
                    for (int q=3;q>r;q--){ tv[q]=tv[q-1]; ti[q]=ti[q-1]; }
                    tv[r]=v; ti[r]=i; break;
                }
            }
        }
        for (int a=0;a<4;a++) for (int c=a+1;c<4;c++)
            if (ti[c] < ti[a]) { int t=ti[a]; ti[a]=ti[c]; ti[c]=t; }
        for (int r=0;r<4;r++) g_topk[b*4+r] = ti[r];
    }
}

// ---------------- 9. output projection: attn_out = ctx @ Wo ----------------
__global__ void k_oproj(const float* __restrict__ Wo, float* __restrict__ out) {
    __shared__ float h_sm[Bb*KC];
    int i0 = blockIdx.y * KC;
    int j  = blockIdx.x * 512 + threadIdx.x * 4;
    for (int idx = threadIdx.x; idx < Bb*KC; idx += blockDim.x)
        h_sm[idx] = g_ctx[(idx/KC)*Dd + i0 + (idx%KC)];
    __syncthreads();
    float4 acc[Bb];
    #pragma unroll
    for (int b=0;b<Bb;b++) acc[b] = make_float4(0.f,0.f,0.f,0.f);
    const float4* Wp = (const float4*)(Wo + (size_t)i0*Dd + j);
    for (int ii=0; ii<KC; ii+=4) {
        float4 w0 = Wp[(size_t)(ii+0)*(Dd/4)];
        float4 w1 = Wp[(size_t)(ii+1)*(Dd/4)];
        float4 w2 = Wp[(size_t)(ii+2)*(Dd/4)];
        float4 w3 = Wp[(size_t)(ii+3)*(Dd/4)];
        #pragma unroll
        for (int b=0;b<Bb;b++) {
            float h0 = h_sm[b*KC+ii+0], h1 = h_sm[b*KC+ii+1];
            float h2 = h_sm[b*KC+ii+2], h3 = h_sm[b*KC+ii+3];
            acc[b].x += h0*w0.x + h1*w1.x + h2*w2.x + h3*w3.x;
            acc[b].y += h0*w0.y + h1*w1.y + h2*w2.y + h3*w3.y;
            acc[b].z += h0*w0.z + h1*w1.z + h2*w2.z + h3*w3.z;
            acc[b].w += h0*w0.w + h1*w1.w + h2*w2.w + h3*w3.w;
        }
    }
    #pragma unroll
    for (int b=0;b<Bb;b++) {
        atomicAdd(&out[b*Dd+j  ], acc[b].x);
        atomicAdd(&out[b*Dd+j+1], acc[b].y);
        atomicAdd(&out[b*Dd+j+2], acc[b].z);
        atomicAdd(&out[b*Dd+j+3], acc[b].w);
    }
}

// ---------------- 10. eviction gather of K/V (float4, 4 slots/block) ----------------
__global__ void k_gather(const float* __restrict__ Kc, const float* __restrict__ Vc,
                         float* __restrict__ out) {
    int bh = blockIdx.y;        // 0..255
    int b = bh >> 5, h = bh & 31;
    int j = blockIdx.x*4 + (threadIdx.x >> 5);   // keep slot
    int lane = threadIdx.x & 31;
    if (j >= KEEP) return;
    int idx = (j < 4) ? g_topk[b*4+j] : (CAND + (j-4));
    float4 kv, vv;
    if (idx < Ss) {
        size_t off = ((size_t)bh*Ss + idx)*32 + lane;
        kv = ((const float4*)Kc)[off];
        vv = ((const float4*)Vc)[off];
    } else {
        int o = (b*Dd + h*HD)/4 + lane;
        kv = ((const float4*)g_k)[o];
        vv = ((const float4*)g_v)[o];
    }
    size_t doff = ((size_t)bh*KEEP + j)*32 + lane;
    ((float4*)(out + OFF_K))[doff] = kv;
    ((float4*)(out + OFF_V))[doff] = vv;
}

// ---------------- 11. imp_kept gather ----------------
__global__ void k_impkept(float* __restrict__ out) {
    int b = blockIdx.x;
    for (int j = threadIdx.x; j < KEEP; j += blockDim.x) {
        int idx = (j < 4) ? g_topk[b*4+j] : (CAND + (j-4));
        out[OFF_IMP + b*KEEP + j] = g_imp[b*KV + idx];
    }
}

// ---------------- launch ----------------
extern "C" void kernel_launch(void* const* d_in, const int* in_sizes, int n_in,
                              void* d_out, int out_size) {
    const float* hs   = (const float*)d_in[0];
    const float* pk   = (const float*)d_in[1];
    const float* pv   = (const float*)d_in[2];
    const float* Wq   = (const float*)d_in[3];
    const float* Wk   = (const float*)d_in[4];
    const float* Wv   = (const float*)d_in[5];
    const float* Wo   = (const float*)d_in[6];
    const float* prev = (const float*)d_in[7];
    float* out = (float*)d_out;

    k_zero   <<<(Bb*Dd + 255)/256, 256>>>(out);
    k_proj   <<<dim3(Dd/512, Dd/KC, 3), 128>>>(hs, Wq, Wk, Wv);
    k_rope   <<<Bb*Hh, HD>>>();
    k_scores <<<dim3(4, Bb*Hh), 256>>>(pk);
    k_ml     <<<Bb*Hh, 128>>>();
    k_ctx    <<<dim3(4, Bb*Hh), 256>>>(pv);
    k_imp    <<<(Bb*KV + 255)/256, 256>>>(prev);
    k_topk   <<<Bb, 256>>>();
    k_oproj  <<<dim3(Dd/512, Dd/KC), 128>>>(Wo, out);
    k_gather <<<dim3((KEEP+3)/4, Bb*Hh), 128>>>(pk, pv, out);
    k_impkept<<<Bb, 256>>>(out);
}

// round 5
// speedup vs baseline: 1.4481x; 1.1024x over previous
#include <cuda_runtime.h>
#include <math.h>

#define Bb   8
#define Hh   32
#define Ss   4096
#define HD   128
#define Dd   4096
#define KV   4097          // Ss + 1 new token
#define SSTR 4112          // padded score stride
#define CAND 3585          // KV - RECENT(512)
#define KEEP 516           // IMP_SIZE(4) + RECENT(512)
#define KC   128           // split-K chunk for projections
#define NPART 64           // split-K partials per (b,h): 8 chunks x 8 warps

#define OFF_K   32768
#define OFF_V   (32768 + 16908288)
#define OFF_IMP (32768 + 2*16908288)

// ---------------- static scratch (no allocations allowed) ----------------
__device__ float g_q[Bb*Dd];
__device__ float g_k[Bb*Dd];
__device__ float g_v[Bb*Dd];
__device__ float g_scores[Bb*Hh*SSTR];
__device__ float g_m[Bb*Hh];
__device__ float g_il[Bb*Hh];        // 1/l
__device__ float g_ctx[Bb*Hh*HD];    // == Bb*Dd floats
__device__ float g_imp[Bb*KV];
__device__ int   g_topk[Bb*4];
__device__ float g_pm[Bb*Hh*NPART];
__device__ float g_pl[Bb*Hh*NPART];
__device__ float g_pctx[Bb*Hh*NPART*HD];   // 8 MB partial ctx

// ---------------- 1. zero accumulators ----------------
__global__ void k_zero(float* out0) {
    int i = blockIdx.x*blockDim.x + threadIdx.x;
    if (i < Bb*Dd) { g_q[i]=0.f; g_k[i]=0.f; g_v[i]=0.f; out0[i]=0.f; }
}

// ---------------- 2. QKV projection: out[b][j] = sum_i h[b][i]*W[i][j] ----------------
__global__ void k_proj(const float* __restrict__ hs,
                       const float* __restrict__ Wq,
                       const float* __restrict__ Wk,
                       const float* __restrict__ Wv) {
    __shared__ float h_sm[Bb*KC];
    int w = blockIdx.z;
    const float* W = (w==0) ? Wq : ((w==1) ? Wk : Wv);
    float* out     = (w==0) ? g_q : ((w==1) ? g_k : g_v);
    int i0 = blockIdx.y * KC;
    int j  = blockIdx.x * 512 + threadIdx.x * 4;

    for (int idx = threadIdx.x; idx < Bb*KC; idx += blockDim.x)
        h_sm[idx] = hs[(idx/KC)*Dd + i0 + (idx%KC)];
    __syncthreads();

    float4 acc[Bb];
    #pragma unroll
    for (int b=0;b<Bb;b++) acc[b] = make_float4(0.f,0.f,0.f,0.f);

    const float4* Wp = (const float4*)(W + (size_t)i0*Dd + j);
    for (int ii=0; ii<KC; ii+=4) {
        float4 w0 = Wp[(size_t)(ii+0)*(Dd/4)];
        float4 w1 = Wp[(size_t)(ii+1)*(Dd/4)];
        float4 w2 = Wp[(size_t)(ii+2)*(Dd/4)];
        float4 w3 = Wp[(size_t)(ii+3)*(Dd/4)];
        #pragma unroll
        for (int b=0;b<Bb;b++) {
            float h0 = h_sm[b*KC+ii+0], h1 = h_sm[b*KC+ii+1];
            float h2 = h_sm[b*KC+ii+2], h3 = h_sm[b*KC+ii+3];
            acc[b].x += h0*w0.x + h1*w1.x + h2*w2.x + h3*w3.x;
            acc[b].y += h0*w0.y + h1*w1.y + h2*w2.y + h3*w3.y;
            acc[b].z += h0*w0.z + h1*w1.z + h2*w2.z + h3*w3.z;
            acc[b].w += h0*w0.w + h1*w1.w + h2*w2.w + h3*w3.w;
        }
    }
    #pragma unroll
    for (int b=0;b<Bb;b++) {
        atomicAdd(&out[b*Dd+j  ], acc[b].x);
        atomicAdd(&out[b*Dd+j+1], acc[b].y);
        atomicAdd(&out[b*Dd+j+2], acc[b].z);
        atomicAdd(&out[b*Dd+j+3], acc[b].w);
    }
}

// ---------------- 3. RoPE (position S) + new-token score ----------------
__global__ void k_rope() {
    __shared__ float qs[HD], ks[HD], red[HD];
    int bh = blockIdx.x;
    int d  = threadIdx.x;
    int base = (bh/Hh)*Dd + (bh%Hh)*HD;
    qs[d] = g_q[base+d]; ks[d] = g_k[base+d];
    __syncthreads();
    int i = d & 63;
    double ang = 4096.0 * pow(10000.0, -(double)(2*i)/128.0);
    float c = (float)cos(ang), s = (float)sin(ang);
    float qr = (d<64) ? -qs[d+64] : qs[d-64];
    float kr = (d<64) ? -ks[d+64] : ks[d-64];
    float qn = qs[d]*c + qr*s;
    float kn = ks[d]*c + kr*s;
    g_q[base+d]=qn; g_k[base+d]=kn;
    red[d] = qn*kn;
    __syncthreads();
    for (int st=64; st>0; st>>=1) { if (d<st) red[d]+=red[d+st]; __syncthreads(); }
    if (d==0) g_scores[(size_t)bh*SSTR + Ss] = red[0] * 0.08838834764831845f;
}

// ---------------- 4. fused scores + online-softmax ctx (1 GB stream) ----------------
// grid (8, Bb*Hh), 256 threads (8 warps). warp handles 64 contiguous tokens.
__global__ void k_fused(const float* __restrict__ Kc, const float* __restrict__ Vc) {
    int bh   = blockIdx.y;
    int warp = threadIdx.x >> 5, lane = threadIdx.x & 31;
    int s0   = blockIdx.x*512 + warp*64;
    float4 q4 = ((const float4*)(g_q + (bh/Hh)*Dd + (bh%Hh)*HD))[lane];
    const float4* Kp = (const float4*)Kc + (size_t)bh*Ss*32;
    const float4* Vp = (const float4*)Vc + (size_t)bh*Ss*32;
    float* sc = g_scores + (size_t)bh*SSTR;
    const float scale = 0.08838834764831845f;

    float m = -1e30f, l = 0.f;
    float4 acc = make_float4(0.f,0.f,0.f,0.f);

    for (int s = s0; s < s0+64; s += 4) {
        float4 k0 = Kp[(size_t)(s+0)*32 + lane];
        float4 k1 = Kp[(size_t)(s+1)*32 + lane];
        float4 k2 = Kp[(size_t)(s+2)*32 + lane];
        float4 k3 = Kp[(size_t)(s+3)*32 + lane];
        float4 v0 = Vp[(size_t)(s+0)*32 + lane];
        float4 v1 = Vp[(size_t)(s+1)*32 + lane];
        float4 v2 = Vp[(size_t)(s+2)*32 + lane];
        float4 v3 = Vp[(size_t)(s+3)*32 + lane];
        float d0 = q4.x*k0.x + q4.y*k0.y + q4.z*k0.z + q4.w*k0.w;
        float d1 = q4.x*k1.x + q4.y*k1.y + q4.z*k1.z + q4.w*k1.w;
        float d2 = q4.x*k2.x + q4.y*k2.y + q4.z*k2.z + q4.w*k2.w;
        float d3 = q4.x*k3.x + q4.y*k3.y + q4.z*k3.z + q4.w*k3.w;
        #pragma unroll
        for (int off=16; off; off>>=1) {
            d0 += __shfl_xor_sync(0xFFFFFFFFu, d0, off);
            d1 += __shfl_xor_sync(0xFFFFFFFFu, d1, off);
            d2 += __shfl_xor_sync(0xFFFFFFFFu, d2, off);
            d3 += __shfl_xor_sync(0xFFFFFFFFu, d3, off);
        }
        d0 *= scale; d1 *= scale; d2 *= scale; d3 *= scale;
        if (lane == 0) { sc[s]=d0; sc[s+1]=d1; sc[s+2]=d2; sc[s+3]=d3; }
        float gm = fmaxf(m, fmaxf(fmaxf(d0,d1), fmaxf(d2,d3)));
        float r  = expf(m - gm);
        float p0 = expf(d0-gm), p1 = expf(d1-gm);
        float p2 = expf(d2-gm), p3 = expf(d3-gm);
        l = l*r + (p0+p1) + (p2+p3);
        acc.x = acc.x*r + p0*v0.x + p1*v1.x + p2*v2.x + p3*v3.x;
        acc.y = acc.y*r + p0*v0.y + p1*v1.y + p2*v2.y + p3*v3.y;
        acc.z = acc.z*r + p0*v0.z + p1*v1.z + p2*v2.z + p3*v3.z;
        acc.w = acc.w*r + p0*v0.w + p1*v1.w + p2*v2.w + p3*v3.w;
        m = gm;
    }
    int pid = bh*NPART + blockIdx.x*8 + warp;
    if (lane == 0) { g_pm[pid] = m; g_pl[pid] = l; }
    ((float4*)g_pctx)[(size_t)pid*32 + lane] = acc;
}

// ---------------- 5. combine partials -> ctx, m, 1/l ----------------
__global__ void k_comb() {
    int bh = blockIdx.x;
    int d  = threadIdx.x;                  // 128 threads
    __shared__ float sm_m[NPART], sm_l[NPART], sm_w[NPART];
    if (d < NPART) { sm_m[d] = g_pm[bh*NPART+d]; sm_l[d] = g_pl[bh*NPART+d]; }
    __syncthreads();
    float sNew = g_scores[(size_t)bh*SSTR + Ss];
    float M = sNew;
    #pragma unroll 8
    for (int i=0;i<NPART;i++) M = fmaxf(M, sm_m[i]);
    __syncthreads();
    if (d < NPART) sm_w[d] = expf(sm_m[d]-M);
    __syncthreads();
    float pNew = expf(sNew - M);
    float L = pNew;
    #pragma unroll 8
    for (int i=0;i<NPART;i++) L += sm_l[i]*sm_w[i];
    const float* pc = g_pctx + (size_t)bh*NPART*HD + d;
    float a = 0.f;
    #pragma unroll 4
    for (int i=0;i<NPART;i++) a += sm_w[i] * pc[(size_t)i*HD];
    a += pNew * g_v[(bh/Hh)*Dd + (bh%Hh)*HD + d];
    float invL = 1.0f / L;
    g_ctx[bh*HD + d] = a * invL;
    if (d == 0) { g_m[bh] = M; g_il[bh] = invL; }
}

// ---------------- 6. importance: mean over heads + prev ----------------
__global__ void k_imp(const float* __restrict__ prev) {
    int idx = blockIdx.x*256 + threadIdx.x;
    if (idx >= Bb*KV) return;
    int b = idx / KV, s = idx % KV;
    float v = 0.f;
    #pragma unroll 4
    for (int h=0; h<Hh; h++) {
        int bh = b*Hh + h;
        v += expf(g_scores[(size_t)bh*SSTR + s] - g_m[bh]) * g_il[bh];
    }
    v *= (1.0f/32.0f);
    if (s < Ss) v += prev[b*Ss + s];
    g_imp[idx] = v;
}

// ---------------- 7. per-batch top-4 over imp[:CAND] ----------------
__global__ void k_topk() {
    int b = blockIdx.x;
    const float* imp = g_imp + b*KV;
    float bv[4]; int bi[4];
    #pragma unroll
    for (int r=0;r<4;r++){ bv[r]=-1e30f; bi[r]=0x7FFFFFFF; }
    for (int s = threadIdx.x; s < CAND; s += 256) {
        float v = imp[s];
        #pragma unroll
        for (int r=0;r<4;r++) {
            if (v > bv[r] || (v == bv[r] && s < bi[r])) {
                for (int q=3;q>r;q--){ bv[q]=bv[q-1]; bi[q]=bi[q-1]; }
                bv[r]=v; bi[r]=s; break;
            }
        }
    }
    __shared__ float sv[1024];
    __shared__ int   si[1024];
    #pragma unroll
    for (int r=0;r<4;r++){ sv[threadIdx.x*4+r]=bv[r]; si[threadIdx.x*4+r]=bi[r]; }
    __syncthreads();
    if (threadIdx.x == 0) {
        float tv[4]; int ti[4];
        #pragma unroll
        for (int r=0;r<4;r++){ tv[r]=-1e30f; ti[r]=0x7FFFFFFF; }
        for (int e=0;e<1024;e++) {
            float v = sv[e]; int i = si[e];
            for (int r=0;r<4;r++) {
                if (v > tv[r] || (v == tv[r] && i < ti[r])) {
                    for (int q=3;q>r;q--){ tv[q]=tv[q-1]; ti[q]=ti[q-1]; }
                    tv[r]=v; ti[r]=i; break;
                }
            }
        }
        for (int a=0;a<4;a++) for (int c=a+1;c<4;c++)
            if (ti[c] < ti[a]) { int t=ti[a]; ti[a]=ti[c]; ti[c]=t; }
        for (int r=0;r<4;r++) g_topk[b*4+r] = ti[r];
    }
}

// ---------------- 8. output projection: attn_out = ctx @ Wo ----------------
__global__ void k_oproj(const float* __restrict__ Wo, float* __restrict__ out) {
    __shared__ float h_sm[Bb*KC];
    int i0 = blockIdx.y * KC;
    int j  = blockIdx.x * 512 + threadIdx.x * 4;
    for (int idx = threadIdx.x; idx < Bb*KC; idx += blockDim.x)
        h_sm[idx] = g_ctx[(idx/KC)*Dd + i0 + (idx%KC)];
    __syncthreads();
    float4 acc[Bb];
    #pragma unroll
    for (int b=0;b<Bb;b++) acc[b] = make_float4(0.f,0.f,0.f,0.f);
    const float4* Wp = (const float4*)(Wo + (size_t)i0*Dd + j);
    for (int ii=0; ii<KC; ii+=4) {
        float4 w0 = Wp[(size_t)(ii+0)*(Dd/4)];
        float4 w1 = Wp[(size_t)(ii+1)*(Dd/4)];
        float4 w2 = Wp[(size_t)(ii+2)*(Dd/4)];
        float4 w3 = Wp[(size_t)(ii+3)*(Dd/4)];
        #pragma unroll
        for (int b=0;b<Bb;b++) {
            float h0 = h_sm[b*KC+ii+0], h1 = h_sm[b*KC+ii+1];
            float h2 = h_sm[b*KC+ii+2], h3 = h_sm[b*KC+ii+3];
            acc[b].x += h0*w0.x + h1*w1.x + h2*w2.x + h3*w3.x;
            acc[b].y += h0*w0.y + h1*w1.y + h2*w2.y + h3*w3.y;
            acc[b].z += h0*w0.z + h1*w1.z + h2*w2.z + h3*w3.z;
            acc[b].w += h0*w0.w + h1*w1.w + h2*w2.w + h3*w3.w;
        }
    }
    #pragma unroll
    for (int b=0;b<Bb;b++) {
        atomicAdd(&out[b*Dd+j  ], acc[b].x);
        atomicAdd(&out[b*Dd+j+1], acc[b].y);
        atomicAdd(&out[b*Dd+j+2], acc[b].z);
        atomicAdd(&out[b*Dd+j+3], acc[b].w);
    }
}

// ---------------- 9. eviction gather of K/V (float4, 4 slots/block) ----------------
__global__ void k_gather(const float* __restrict__ Kc, const float* __restrict__ Vc,
                         float* __restrict__ out) {
    int bh = blockIdx.y;        // 0..255
    int b = bh >> 5, h = bh & 31;
    int j = blockIdx.x*4 + (threadIdx.x >> 5);   // keep slot
    int lane = threadIdx.x & 31;
    if (j >= KEEP) return;
    int idx = (j < 4) ? g_topk[b*4+j] : (CAND + (j-4));
    float4 kv, vv;
    if (idx < Ss) {
        size_t off = ((size_t)bh*Ss + idx)*32 + lane;
        kv = ((const float4*)Kc)[off];
        vv = ((const float4*)Vc)[off];
    } else {
        int o = (b*Dd + h*HD)/4 + lane;
        kv = ((const float4*)g_k)[o];
        vv = ((const float4*)g_v)[o];
    }
    size_t doff = ((size_t)bh*KEEP + j)*32 + lane;
    ((float4*)(out + OFF_K))[doff] = kv;
    ((float4*)(out + OFF_V))[doff] = vv;
}

// ---------------- 10. imp_kept gather ----------------
__global__ void k_impkept(float* __restrict__ out) {
    int b = blockIdx.x;
    for (int j = threadIdx.x; j < KEEP; j += blockDim.x) {
        int idx = (j < 4) ? g_topk[b*4+j] : (CAND + (j-4));
        out[OFF_IMP + b*KEEP + j] = g_imp[b*KV + idx];
    }
}

// ---------------- launch ----------------
extern "C" void kernel_launch(void* const* d_in, const int* in_sizes, int n_in,
                              void* d_out, int out_size) {
    const float* hs   = (const float*)d_in[0];
    const float* pk   = (const float*)d_in[1];
    const float* pv   = (const float*)d_in[2];
    const float* Wq   = (const float*)d_in[3];
    const float* Wk   = (const float*)d_in[4];
    const float* Wv   = (const float*)d_in[5];
    const float* Wo   = (const float*)d_in[6];
    const float* prev = (const float*)d_in[7];
    float* out = (float*)d_out;

    k_zero   <<<(Bb*Dd + 255)/256, 256>>>(out);
    k_proj   <<<dim3(Dd/512, Dd/KC, 3), 128>>>(hs, Wq, Wk, Wv);
    k_rope   <<<Bb*Hh, HD>>>();
    k_fused  <<<dim3(8, Bb*Hh), 256>>>(pk, pv);
    k_comb   <<<Bb*Hh, 128>>>();
    k_imp    <<<(Bb*KV + 255)/256, 256>>>(prev);
    k_topk   <<<Bb, 256>>>();
    k_oproj  <<<dim3(Dd/512, Dd/KC), 128>>>(Wo, out);
    k_gather <<<dim3((KEEP+3)/4, Bb*Hh), 128>>>(pk, pv, out);
    k_impkept<<<Bb, 256>>>(out);
}

// round 6
// speedup vs baseline: 1.5182x; 1.0484x over previous
#include <cuda_runtime.h>
#include <math.h>

#define Bb   8
#define Hh   32
#define Ss   4096
#define HD   128
#define Dd   4096
#define KV   4097          // Ss + 1 new token
#define SSTR 4112          // padded score stride
#define CAND 3585          // KV - RECENT(512)
#define KEEP 516           // IMP_SIZE(4) + RECENT(512)
#define KC   64            // split-K chunk for projections
#define NPART 64           // split-K partials per (b,h): 8 chunks x 8 warps

#define OFF_K   32768
#define OFF_V   (32768 + 16908288)
#define OFF_IMP (32768 + 2*16908288)

// ---------------- static scratch (no allocations allowed) ----------------
__device__ float g_q[Bb*Dd];
__device__ float g_k[Bb*Dd];
__device__ float g_v[Bb*Dd];
__device__ float g_scores[Bb*Hh*SSTR];
__device__ float g_m[Bb*Hh];
__device__ float g_il[Bb*Hh];        // 1/l
__device__ float g_ctx[Bb*Hh*HD];    // == Bb*Dd floats
__device__ float g_imp[Bb*KV];
__device__ int   g_topk[Bb*4];
__device__ float g_pm[Bb*Hh*NPART];
__device__ float g_pl[Bb*Hh*NPART];
__device__ float g_pctx[Bb*Hh*NPART*HD];   // 8 MB partial ctx

// ---------------- 1. zero accumulators ----------------
__global__ void k_zero(float* out0) {
    int i = blockIdx.x*blockDim.x + threadIdx.x;
    if (i < Bb*Dd) { g_q[i]=0.f; g_k[i]=0.f; g_v[i]=0.f; out0[i]=0.f; }
}

// ---------------- 2. QKV projection: out[b][j] = sum_i h[b][i]*W[i][j] ----------------
__global__ void k_proj(const float* __restrict__ hs,
                       const float* __restrict__ Wq,
                       const float* __restrict__ Wk,
                       const float* __restrict__ Wv) {
    __shared__ float h_sm[Bb*KC];
    int w = blockIdx.z;
    const float* W = (w==0) ? Wq : ((w==1) ? Wk : Wv);
    float* out     = (w==0) ? g_q : ((w==1) ? g_k : g_v);
    int i0 = blockIdx.y * KC;
    int j  = blockIdx.x * 512 + threadIdx.x * 4;

    for (int idx = threadIdx.x; idx < Bb*KC; idx += blockDim.x)
        h_sm[idx] = hs[(idx/KC)*Dd + i0 + (idx%KC)];
    __syncthreads();

    float4 acc[Bb];
    #pragma unroll
    for (int b=0;b<Bb;b++) acc[b] = make_float4(0.f,0.f,0.f,0.f);

    const float4* Wp = (const float4*)(W + (size_t)i0*Dd + j);
    for (int ii=0; ii<KC; ii+=4) {
        float4 w0 = Wp[(size_t)(ii+0)*(Dd/4)];
        float4 w1 = Wp[(size_t)(ii+1)*(Dd/4)];
        float4 w2 = Wp[(size_t)(ii+2)*(Dd/4)];
        float4 w3 = Wp[(size_t)(ii+3)*(Dd/4)];
        #pragma unroll
        for (int b=0;b<Bb;b++) {
            float h0 = h_sm[b*KC+ii+0], h1 = h_sm[b*KC+ii+1];
            float h2 = h_sm[b*KC+ii+2], h3 = h_sm[b*KC+ii+3];
            acc[b].x += h0*w0.x + h1*w1.x + h2*w2.x + h3*w3.x;
            acc[b].y += h0*w0.y + h1*w1.y + h2*w2.y + h3*w3.y;
            acc[b].z += h0*w0.z + h1*w1.z + h2*w2.z + h3*w3.z;
            acc[b].w += h0*w0.w + h1*w1.w + h2*w2.w + h3*w3.w;
        }
    }
    #pragma unroll
    for (int b=0;b<Bb;b++) {
        atomicAdd(&out[b*Dd+j  ], acc[b].x);
        atomicAdd(&out[b*Dd+j+1], acc[b].y);
        atomicAdd(&out[b*Dd+j+2], acc[b].z);
        atomicAdd(&out[b*Dd+j+3], acc[b].w);
    }
}

// ---------------- 3. RoPE (position S) + new-token score ----------------
__global__ void k_rope() {
    __shared__ float qs[HD], ks[HD], red[HD];
    int bh = blockIdx.x;
    int d  = threadIdx.x;
    int base = (bh/Hh)*Dd + (bh%Hh)*HD;
    qs[d] = g_q[base+d]; ks[d] = g_k[base+d];
    __syncthreads();
    int i = d & 63;
    double ang = 4096.0 * pow(10000.0, -(double)(2*i)/128.0);
    float c = (float)cos(ang), s = (float)sin(ang);
    float qr = (d<64) ? -qs[d+64] : qs[d-64];
    float kr = (d<64) ? -ks[d+64] : ks[d-64];
    float qn = qs[d]*c + qr*s;
    float kn = ks[d]*c + kr*s;
    g_q[base+d]=qn; g_k[base+d]=kn;
    red[d] = qn*kn;
    __syncthreads();
    for (int st=64; st>0; st>>=1) { if (d<st) red[d]+=red[d+st]; __syncthreads(); }
    if (d==0) g_scores[(size_t)bh*SSTR + Ss] = red[0] * 0.08838834764831845f;
}

// ---------------- 4. fused scores + online-softmax ctx + recent-window evict copy ----------------
// grid (8, Bb*Hh), 256 threads (8 warps). warp handles 64 contiguous tokens.
__global__ void k_fused(const float* __restrict__ Kc, const float* __restrict__ Vc,
                        float* __restrict__ out) {
    int bh   = blockIdx.y;
    int warp = threadIdx.x >> 5, lane = threadIdx.x & 31;
    int s0   = blockIdx.x*512 + warp*64;
    float4 q4 = ((const float4*)(g_q + (bh/Hh)*Dd + (bh%Hh)*HD))[lane];
    const float4* Kp = (const float4*)Kc + (size_t)bh*Ss*32;
    const float4* Vp = (const float4*)Vc + (size_t)bh*Ss*32;
    float4* outK = (float4*)(out + OFF_K) + (size_t)bh*KEEP*32 + lane;
    float4* outV = (float4*)(out + OFF_V) + (size_t)bh*KEEP*32 + lane;
    float* sc = g_scores + (size_t)bh*SSTR;
    const float scale = 0.08838834764831845f;

    float m = -1e30f, l = 0.f;
    float4 acc = make_float4(0.f,0.f,0.f,0.f);

    for (int s = s0; s < s0+64; s += 4) {
        float4 k0 = Kp[(size_t)(s+0)*32 + lane];
        float4 k1 = Kp[(size_t)(s+1)*32 + lane];
        float4 k2 = Kp[(size_t)(s+2)*32 + lane];
        float4 k3 = Kp[(size_t)(s+3)*32 + lane];
        float4 v0 = Vp[(size_t)(s+0)*32 + lane];
        float4 v1 = Vp[(size_t)(s+1)*32 + lane];
        float4 v2 = Vp[(size_t)(s+2)*32 + lane];
        float4 v3 = Vp[(size_t)(s+3)*32 + lane];
        float d0 = q4.x*k0.x + q4.y*k0.y + q4.z*k0.z + q4.w*k0.w;
        float d1 = q4.x*k1.x + q4.y*k1.y + q4.z*k1.z + q4.w*k1.w;
        float d2 = q4.x*k2.x + q4.y*k2.y + q4.z*k2.z + q4.w*k2.w;
        float d3 = q4.x*k3.x + q4.y*k3.y + q4.z*k3.z + q4.w*k3.w;
        #pragma unroll
        for (int off=16; off; off>>=1) {
            d0 += __shfl_xor_sync(0xFFFFFFFFu, d0, off);
            d1 += __shfl_xor_sync(0xFFFFFFFFu, d1, off);
            d2 += __shfl_xor_sync(0xFFFFFFFFu, d2, off);
            d3 += __shfl_xor_sync(0xFFFFFFFFu, d3, off);
        }
        d0 *= scale; d1 *= scale; d2 *= scale; d3 *= scale;
        if (lane == 0) { sc[s]=d0; sc[s+1]=d1; sc[s+2]=d2; sc[s+3]=d3; }
        // recent-window eviction copy: tokens [CAND, Ss) -> keep slot 4 + (tok-CAND)
        if (s+3 >= CAND) {
            if (s+0 >= CAND) { outK[(size_t)(s+0-CAND+4)*32]=k0; outV[(size_t)(s+0-CAND+4)*32]=v0; }
            if (s+1 >= CAND) { outK[(size_t)(s+1-CAND+4)*32]=k1; outV[(size_t)(s+1-CAND+4)*32]=v1; }
            { outK[(size_t)(s+2-CAND+4)*32]=k2; outV[(size_t)(s+2-CAND+4)*32]=v2; }
            { outK[(size_t)(s+3-CAND+4)*32]=k3; outV[(size_t)(s+3-CAND+4)*32]=v3; }
        }
        float gm = fmaxf(m, fmaxf(fmaxf(d0,d1), fmaxf(d2,d3)));
        float r  = expf(m - gm);
        float p0 = expf(d0-gm), p1 = expf(d1-gm);
        float p2 = expf(d2-gm), p3 = expf(d3-gm);
        l = l*r + (p0+p1) + (p2+p3);
        acc.x = acc.x*r + p0*v0.x + p1*v1.x + p2*v2.x + p3*v3.x;
        acc.y = acc.y*r + p0*v0.y + p1*v1.y + p2*v2.y + p3*v3.y;
        acc.z = acc.z*r + p0*v0.z + p1*v1.z + p2*v2.z + p3*v3.z;
        acc.w = acc.w*r + p0*v0.w + p1*v1.w + p2*v2.w + p3*v3.w;
        m = gm;
    }
    int pid = bh*NPART + blockIdx.x*8 + warp;
    if (lane == 0) { g_pm[pid] = m; g_pl[pid] = l; }
    ((float4*)g_pctx)[(size_t)pid*32 + lane] = acc;
}

// ---------------- 5. combine partials -> ctx, m, 1/l ----------------
__global__ void k_comb() {
    int bh = blockIdx.x;
    int d  = threadIdx.x;                  // 128 threads
    __shared__ float sm_m[NPART], sm_l[NPART], sm_w[NPART];
    if (d < NPART) { sm_m[d] = g_pm[bh*NPART+d]; sm_l[d] = g_pl[bh*NPART+d]; }
    __syncthreads();
    float sNew = g_scores[(size_t)bh*SSTR + Ss];
    float M = sNew;
    #pragma unroll 8
    for (int i=0;i<NPART;i++) M = fmaxf(M, sm_m[i]);
    __syncthreads();
    if (d < NPART) sm_w[d] = expf(sm_m[d]-M);
    __syncthreads();
    float pNew = expf(sNew - M);
    float L = pNew;
    #pragma unroll 8
    for (int i=0;i<NPART;i++) L += sm_l[i]*sm_w[i];
    const float* pc = g_pctx + (size_t)bh*NPART*HD + d;
    float a = 0.f;
    #pragma unroll 4
    for (int i=0;i<NPART;i++) a += sm_w[i] * pc[(size_t)i*HD];
    a += pNew * g_v[(bh/Hh)*Dd + (bh%Hh)*HD + d];
    float invL = 1.0f / L;
    g_ctx[bh*HD + d] = a * invL;
    if (d == 0) { g_m[bh] = M; g_il[bh] = invL; }
}

// ---------------- 6. importance: mean over heads + prev ----------------
__global__ void k_imp(const float* __restrict__ prev) {
    int idx = blockIdx.x*256 + threadIdx.x;
    if (idx >= Bb*KV) return;
    int b = idx / KV, s = idx % KV;
    float v = 0.f;
    #pragma unroll 4
    for (int h=0; h<Hh; h++) {
        int bh = b*Hh + h;
        v += __expf(g_scores[(size_t)bh*SSTR + s] - g_m[bh]) * g_il[bh];
    }
    v *= (1.0f/32.0f);
    if (s < Ss) v += prev[b*Ss + s];
    g_imp[idx] = v;
}

// ---------------- 7. per-batch top-4 over imp[:CAND] ----------------
__global__ void k_topk() {
    int b = blockIdx.x;
    const float* imp = g_imp + b*KV;
    float bv[4]; int bi[4];
    #pragma unroll
    for (int r=0;r<4;r++){ bv[r]=-1e30f; bi[r]=0x7FFFFFFF; }
    for (int s = threadIdx.x; s < CAND; s += 256) {
        float v = imp[s];
        #pragma unroll
        for (int r=0;r<4;r++) {
            if (v > bv[r] || (v == bv[r] && s < bi[r])) {
                for (int q=3;q>r;q--){ bv[q]=bv[q-1]; bi[q]=bi[q-1]; }
                bv[r]=v; bi[r]=s; break;
            }
        }
    }
    __shared__ float sv[1024];
    __shared__ int   si[1024];
    #pragma unroll
    for (int r=0;r<4;r++){ sv[threadIdx.x*4+r]=bv[r]; si[threadIdx.x*4+r]=bi[r]; }
    __syncthreads();
    if (threadIdx.x == 0) {
        float tv[4]; int ti[4];
        #pragma unroll
        for (int r=0;r<4;r++){ tv[r]=-1e30f; ti[r]=0x7FFFFFFF; }
        for (int e=0;e<1024;e++) {
            float v = sv[e]; int i = si[e];
            for (int r=0;r<4;r++) {
                if (v > tv[r] || (v == tv[r] && i < ti[r])) {
                    for (int q=3;q>r;q--){ tv[q]=tv[q-1]; ti[q]=ti[q-1]; }
                    tv[r]=v; ti[r]=i; break;
                }
            }
        }
        for (int a=0;a<4;a++) for (int c=a+1;c<4;c++)
            if (ti[c] < ti[a]) { int t=ti[a]; ti[a]=ti[c]; ti[c]=t; }
        for (int r=0;r<4;r++) g_topk[b*4+r] = ti[r];
    }
}

// ---------------- 8. output projection: attn_out = ctx @ Wo ----------------
__global__ void k_oproj(const float* __restrict__ Wo, float* __restrict__ out) {
    __shared__ float h_sm[Bb*KC];
    int i0 = blockIdx.y * KC;
    int j  = blockIdx.x * 512 + threadIdx.x * 4;
    for (int idx = threadIdx.x; idx < Bb*KC; idx += blockDim.x)
        h_sm[idx] = g_ctx[(idx/KC)*Dd + i0 + (idx%KC)];
    __syncthreads();
    float4 acc[Bb];
    #pragma unroll
    for (int b=0;b<Bb;b++) acc[b] = make_float4(0.f,0.f,0.f,0.f);
    const float4* Wp = (const float4*)(Wo + (size_t)i0*Dd + j);
    for (int ii=0; ii<KC; ii+=4) {
        float4 w0 = Wp[(size_t)(ii+0)*(Dd/4)];
        float4 w1 = Wp[(size_t)(ii+1)*(Dd/4)];
        float4 w2 = Wp[(size_t)(ii+2)*(Dd/4)];
        float4 w3 = Wp[(size_t)(ii+3)*(Dd/4)];
        #pragma unroll
        for (int b=0;b<Bb;b++) {
            float h0 = h_sm[b*KC+ii+0], h1 = h_sm[b*KC+ii+1];
            float h2 = h_sm[b*KC+ii+2], h3 = h_sm[b*KC+ii+3];
            acc[b].x += h0*w0.x + h1*w1.x + h2*w2.x + h3*w3.x;
            acc[b].y += h0*w0.y + h1*w1.y + h2*w2.y + h3*w3.y;
            acc[b].z += h0*w0.z + h1*w1.z + h2*w2.z + h3*w3.z;
            acc[b].w += h0*w0.w + h1*w1.w + h2*w2.w + h3*w3.w;
        }
    }
    #pragma unroll
    for (int b=0;b<Bb;b++) {
        atomicAdd(&out[b*Dd+j  ], acc[b].x);
        atomicAdd(&out[b*Dd+j+1], acc[b].y);
        atomicAdd(&out[b*Dd+j+2], acc[b].z);
        atomicAdd(&out[b*Dd+j+3], acc[b].w);
    }
}

// ---------------- 9. small gather: top-4 rows + new token row ----------------
// grid (Bb*Hh), 160 threads = 5 warps: warps 0..3 -> topk slots, warp 4 -> new token (slot 515)
__global__ void k_gather(const float* __restrict__ Kc, const float* __restrict__ Vc,
                         float* __restrict__ out) {
    int bh = blockIdx.x;
    int b = bh >> 5, h = bh & 31;
    int w = threadIdx.x >> 5, lane = threadIdx.x & 31;
    float4 kv, vv;
    int j;
    if (w < 4) {
        j = w;
        int idx = g_topk[b*4+w];
        size_t off = ((size_t)bh*Ss + idx)*32 + lane;
        kv = ((const float4*)Kc)[off];
        vv = ((const float4*)Vc)[off];
    } else {
        j = KEEP-1;   // 515 -> token 4096 (the new one)
        int o = (b*Dd + h*HD)/4 + lane;
        kv = ((const float4*)g_k)[o];
        vv = ((const float4*)g_v)[o];
    }
    size_t doff = ((size_t)bh*KEEP + j)*32 + lane;
    ((float4*)(out + OFF_K))[doff] = kv;
    ((float4*)(out + OFF_V))[doff] = vv;
}

// ---------------- 10. imp_kept gather ----------------
__global__ void k_impkept(float* __restrict__ out) {
    int b = blockIdx.x;
    for (int j = threadIdx.x; j < KEEP; j += blockDim.x) {
        int idx = (j < 4) ? g_topk[b*4+j] : (CAND + (j-4));
        out[OFF_IMP + b*KEEP + j] = g_imp[b*KV + idx];
    }
}

// ---------------- launch ----------------
extern "C" void kernel_launch(void* const* d_in, const int* in_sizes, int n_in,
                              void* d_out, int out_size) {
    const float* hs   = (const float*)d_in[0];
    const float* pk   = (const float*)d_in[1];
    const float* pv   = (const float*)d_in[2];
    const float* Wq   = (const float*)d_in[3];
    const float* Wk   = (const float*)d_in[4];
    const float* Wv   = (const float*)d_in[5];
    const float* Wo   = (const float*)d_in[6];
    const float* prev = (const float*)d_in[7];
    float* out = (float*)d_out;

    k_zero   <<<(Bb*Dd + 255)/256, 256>>>(out);
    k_proj   <<<dim3(Dd/512, Dd/KC, 3), 128>>>(hs, Wq, Wk, Wv);
    k_rope   <<<Bb*Hh, HD>>>();
    k_fused  <<<dim3(8, Bb*Hh), 256>>>(pk, pv, out);
    k_comb   <<<Bb*Hh, 128>>>();
    k_imp    <<<(Bb*KV + 255)/256, 256>>>(prev);
    k_topk   <<<Bb, 256>>>();
    k_oproj  <<<dim3(Dd/512, Dd/KC), 128>>>(Wo, out);
    k_gather <<<Bb*Hh, 160>>>(pk, pv, out);
    k_impkept<<<Bb, 256>>>(out);
}

// round 9
// speedup vs baseline: 1.7319x; 1.1408x over previous
#include <cuda_runtime.h>
#include <math.h>

#define Bb   8
#define Hh   32
#define Ss   4096
#define HD   128
#define Dd   4096
#define KV   4097          // Ss + 1 new token
#define SSTR 4112          // padded score stride
#define CAND 3585          // KV - RECENT(512)
#define KEEP 516           // IMP_SIZE(4) + RECENT(512)
#define KC   64            // split-K chunk for projections
#define NPART 64           // split-K partials per (b,h): 8 chunks x 8 warps

#define OFF_K   32768
#define OFF_V   (32768 + 16908288)
#define OFF_IMP (32768 + 2*16908288)

// ---------------- static scratch (no allocations allowed) ----------------
__device__ float g_q[Bb*Dd];
__device__ float g_k[Bb*Dd];
__device__ float g_v[Bb*Dd];
__device__ float g_scores[Bb*Hh*SSTR];
__device__ float g_m[Bb*Hh];
__device__ float g_il[Bb*Hh];        // 1/l
__device__ float g_ctx[Bb*Hh*HD];    // == Bb*Dd floats
__device__ float g_imp[Bb*KV];
__device__ int   g_topk[Bb*4];
__device__ float g_pm[Bb*Hh*NPART];
__device__ float g_pl[Bb*Hh*NPART];
__device__ float g_pctx[Bb*Hh*NPART*HD];   // 8 MB partial ctx

__device__ __forceinline__ bool better(float v1, int i1, float v2, int i2) {
    return (v1 > v2) || (v1 == v2 && i1 < i2);
}
__device__ __forceinline__ void ins4(float v, int i, float* bv, int* bi) {
    #pragma unroll
    for (int r=0;r<4;r++) {
        if (better(v, i, bv[r], bi[r])) {
            #pragma unroll
            for (int q=3;q>r;q--){ bv[q]=bv[q-1]; bi[q]=bi[q-1]; }
            bv[r]=v; bi[r]=i; return;
        }
    }
}

// ---------------- 1. zero accumulators ----------------
__global__ void k_zero(float* out0) {
    int i = blockIdx.x*blockDim.x + threadIdx.x;
    if (i < Bb*Dd) { g_q[i]=0.f; g_k[i]=0.f; g_v[i]=0.f; out0[i]=0.f; }
}

// ---------------- 2. QKV projection: out[b][j] = sum_i h[b][i]*W[i][j] ----------------
__global__ void k_proj(const float* __restrict__ hs,
                       const float* __restrict__ Wq,
                       const float* __restrict__ Wk,
                       const float* __restrict__ Wv) {
    __shared__ float h_sm[Bb*KC];
    int w = blockIdx.z;
    const float* W = (w==0) ? Wq : ((w==1) ? Wk : Wv);
    float* out     = (w==0) ? g_q : ((w==1) ? g_k : g_v);
    int i0 = blockIdx.y * KC;
    int j  = blockIdx.x * 512 + threadIdx.x * 4;

    for (int idx = threadIdx.x; idx < Bb*KC; idx += blockDim.x)
        h_sm[idx] = hs[(idx/KC)*Dd + i0 + (idx%KC)];
    __syncthreads();

    float4 acc[Bb];
    #pragma unroll
    for (int b=0;b<Bb;b++) acc[b] = make_float4(0.f,0.f,0.f,0.f);

    const float4* Wp = (const float4*)(W + (size_t)i0*Dd + j);
    for (int ii=0; ii<KC; ii+=4) {
        float4 w0 = __ldcs(&Wp[(size_t)(ii+0)*(Dd/4)]);
        float4 w1 = __ldcs(&Wp[(size_t)(ii+1)*(Dd/4)]);
        float4 w2 = __ldcs(&Wp[(size_t)(ii+2)*(Dd/4)]);
        float4 w3 = __ldcs(&Wp[(size_t)(ii+3)*(Dd/4)]);
        #pragma unroll
        for (int b=0;b<Bb;b++) {
            float h0 = h_sm[b*KC+ii+0], h1 = h_sm[b*KC+ii+1];
            float h2 = h_sm[b*KC+ii+2], h3 = h_sm[b*KC+ii+3];
            acc[b].x += h0*w0.x + h1*w1.x + h2*w2.x + h3*w3.x;
            acc[b].y += h0*w0.y + h1*w1.y + h2*w2.y + h3*w3.y;
            acc[b].z += h0*w0.z + h1*w1.z + h2*w2.z + h3*w3.z;
            acc[b].w += h0*w0.w + h1*w1.w + h2*w2.w + h3*w3.w;
        }
    }
    #pragma unroll
    for (int b=0;b<Bb;b++) {
        atomicAdd(&out[b*Dd+j  ], acc[b].x);
        atomicAdd(&out[b*Dd+j+1], acc[b].y);
        atomicAdd(&out[b*Dd+j+2], acc[b].z);
        atomicAdd(&out[b*Dd+j+3], acc[b].w);
    }
}

// ---------------- 3. RoPE (position S) + new-token score ----------------
__global__ void k_rope() {
    __shared__ float qs[HD], ks[HD], red[HD];
    int bh = blockIdx.x;
    int d  = threadIdx.x;
    int base = (bh/Hh)*Dd + (bh%Hh)*HD;
    qs[d] = g_q[base+d]; ks[d] = g_k[base+d];
    __syncthreads();
    int i = d & 63;
    double ang = 4096.0 * pow(10000.0, -(double)(2*i)/128.0);
    float c = (float)cos(ang), s = (float)sin(ang);
    float qr = (d<64) ? -qs[d+64] : qs[d-64];
    float kr = (d<64) ? -ks[d+64] : ks[d-64];
    float qn = qs[d]*c + qr*s;
    float kn = ks[d]*c + kr*s;
    g_q[base+d]=qn; g_k[base+d]=kn;
    red[d] = qn*kn;
    __syncthreads();
    for (int st=64; st>0; st>>=1) { if (d<st) red[d]+=red[d+st]; __syncthreads(); }
    if (d==0) g_scores[(size_t)bh*SSTR + Ss] = red[0] * 0.08838834764831845f;
}

// ---------------- 4. fused scores + online-softmax ctx + recent-window evict copy ----------------
// grid (8, Bb*Hh), 256 threads (8 warps). warp handles 64 contiguous tokens.
__global__ void k_fused(const float* __restrict__ Kc, const float* __restrict__ Vc,
                        float* __restrict__ out) {
    int bh   = blockIdx.y;
    int warp = threadIdx.x >> 5, lane = threadIdx.x & 31;
    int s0   = blockIdx.x*512 + warp*64;
    float4 q4 = ((const float4*)(g_q + (bh/Hh)*Dd + (bh%Hh)*HD))[lane];
    const float4* Kp = (const float4*)Kc + (size_t)bh*Ss*32;
    const float4* Vp = (const float4*)Vc + (size_t)bh*Ss*32;
    float4* outK = (float4*)(out + OFF_K) + (size_t)bh*KEEP*32 + lane;
    float4* outV = (float4*)(out + OFF_V) + (size_t)bh*KEEP*32 + lane;
    float* sc = g_scores + (size_t)bh*SSTR;
    const float scale = 0.08838834764831845f;

    float m = -1e30f, l = 0.f;
    float4 acc = make_float4(0.f,0.f,0.f,0.f);

    for (int s = s0; s < s0+64; s += 4) {
        float4 k0 = Kp[(size_t)(s+0)*32 + lane];
        float4 k1 = Kp[(size_t)(s+1)*32 + lane];
        float4 k2 = Kp[(size_t)(s+2)*32 + lane];
        float4 k3 = Kp[(size_t)(s+3)*32 + lane];
        float4 v0 = Vp[(size_t)(s+0)*32 + lane];
        float4 v1 = Vp[(size_t)(s+1)*32 + lane];
        float4 v2 = Vp[(size_t)(s+2)*32 + lane];
        float4 v3 = Vp[(size_t)(s+3)*32 + lane];
        float d0 = q4.x*k0.x + q4.y*k0.y + q4.z*k0.z + q4.w*k0.w;
        float d1 = q4.x*k1.x + q4.y*k1.y + q4.z*k1.z + q4.w*k1.w;
        float d2 = q4.x*k2.x + q4.y*k2.y + q4.z*k2.z + q4.w*k2.w;
        float d3 = q4.x*k3.x + q4.y*k3.y + q4.z*k3.z + q4.w*k3.w;
        #pragma unroll
        for (int off=16; off; off>>=1) {
            d0 += __shfl_xor_sync(0xFFFFFFFFu, d0, off);
            d1 += __shfl_xor_sync(0xFFFFFFFFu, d1, off);
            d2 += __shfl_xor_sync(0xFFFFFFFFu, d2, off);
            d3 += __shfl_xor_sync(0xFFFFFFFFu, d3, off);
        }
        d0 *= scale; d1 *= scale; d2 *= scale; d3 *= scale;
        if (lane == 0) { sc[s]=d0; sc[s+1]=d1; sc[s+2]=d2; sc[s+3]=d3; }
        // recent-window eviction copy: tokens [CAND, Ss) -> keep slot 4 + (tok-CAND)
        if (s+3 >= CAND) {
            if (s+0 >= CAND) { outK[(size_t)(s+0-CAND+4)*32]=k0; outV[(size_t)(s+0-CAND+4)*32]=v0; }
            if (s+1 >= CAND) { outK[(size_t)(s+1-CAND+4)*32]=k1; outV[(size_t)(s+1-CAND+4)*32]=v1; }
            { outK[(size_t)(s+2-CAND+4)*32]=k2; outV[(size_t)(s+2-CAND+4)*32]=v2; }
            { outK[(size_t)(s+3-CAND+4)*32]=k3; outV[(size_t)(s+3-CAND+4)*32]=v3; }
        }
        float gm = fmaxf(m, fmaxf(fmaxf(d0,d1), fmaxf(d2,d3)));
        float r  = expf(m - gm);
        float p0 = expf(d0-gm), p1 = expf(d1-gm);
        float p2 = expf(d2-gm), p3 = expf(d3-gm);
        l = l*r + (p0+p1) + (p2+p3);
        acc.x = acc.x*r + p0*v0.x + p1*v1.x + p2*v2.x + p3*v3.x;
        acc.y = acc.y*r + p0*v0.y + p1*v1.y + p2*v2.y + p3*v3.y;
        acc.z = acc.z*r + p0*v0.z + p1*v1.z + p2*v2.z + p3*v3.z;
        acc.w = acc.w*r + p0*v0.w + p1*v1.w + p2*v2.w + p3*v3.w;
        m = gm;
    }
    int pid = bh*NPART + blockIdx.x*8 + warp;
    if (lane == 0) { g_pm[pid] = m; g_pl[pid] = l; }
    ((float4*)g_pctx)[(size_t)pid*32 + lane] = acc;
}

// ---------------- 5. combine partials -> ctx, m, 1/l; also emit new-token evict row ----------------
__global__ void k_comb(float* __restrict__ out) {
    int bh = blockIdx.x;
    int d  = threadIdx.x;                  // 128 threads
    __shared__ float sm_m[NPART], sm_l[NPART], sm_w[NPART];
    if (d < NPART) { sm_m[d] = g_pm[bh*NPART+d]; sm_l[d] = g_pl[bh*NPART+d]; }
    __syncthreads();
    float sNew = g_scores[(size_t)bh*SSTR + Ss];
    float M = sNew;
    #pragma unroll 8
    for (int i=0;i<NPART;i++) M = fmaxf(M, sm_m[i]);
    __syncthreads();
    if (d < NPART) sm_w[d] = expf(sm_m[d]-M);
    __syncthreads();
    float pNew = expf(sNew - M);
    float L = pNew;
    #pragma unroll 8
    for (int i=0;i<NPART;i++) L += sm_l[i]*sm_w[i];
    const float* pc = g_pctx + (size_t)bh*NPART*HD + d;
    float a = 0.f;
    #pragma unroll 4
    for (int i=0;i<NPART;i++) a += sm_w[i] * pc[(size_t)i*HD];
    int nb = (bh/Hh)*Dd + (bh%Hh)*HD + d;
    float vNew = g_v[nb];
    a += pNew * vNew;
    float invL = 1.0f / L;
    g_ctx[bh*HD + d] = a * invL;
    if (d == 0) { g_m[bh] = M; g_il[bh] = invL; }
    // eviction output for the NEW token -> keep slot 515
    size_t doff = ((size_t)bh*KEEP + (KEEP-1))*HD + d;
    out[OFF_K + doff] = g_k[nb];
    out[OFF_V + doff] = vNew;
}

// ---------------- 6. importance: mean over heads + prev ----------------
__global__ void k_imp(const float* __restrict__ prev) {
    int idx = blockIdx.x*256 + threadIdx.x;
    if (idx >= Bb*KV) return;
    int b = idx / KV, s = idx % KV;
    float v = 0.f;
    #pragma unroll 4
    for (int h=0; h<Hh; h++) {
        int bh = b*Hh + h;
        v += __expf(g_scores[(size_t)bh*SSTR + s] - g_m[bh]) * g_il[bh];
    }
    v *= (1.0f/32.0f);
    if (s < Ss) v += prev[b*Ss + s];
    g_imp[idx] = v;
}

// ---------------- 7. per-batch: top-4 + imp_kept + top-4 K/V gather (one kernel) ----------------
__global__ void k_topk(const float* __restrict__ Kc, const float* __restrict__ Vc,
                       float* __restrict__ out) {
    int b = blockIdx.x;
    int tid = threadIdx.x;                 // 256 threads
    const float* imp = g_imp + b*KV;
    float bv[4]; int bi[4];
    #pragma unroll
    for (int r=0;r<4;r++){ bv[r]=-1e30f; bi[r]=0x7FFFFFFF; }
    for (int s = tid; s < CAND; s += 256) ins4(imp[s], s, bv, bi);

    __shared__ float sv[1024];
    __shared__ int   si[1024];
    __shared__ int   tk[4];
    #pragma unroll
    for (int r=0;r<4;r++){ sv[tid*4+r]=bv[r]; si[tid*4+r]=bi[r]; }
    __syncthreads();

    // level 1: warp 0, each lane merges 8 thread-lists (32 entries)
    if (tid < 32) {
        float mv[4]; int mi[4];
        #pragma unroll
        for (int r=0;r<4;r++){ mv[r]=-1e30f; mi[r]=0x7FFFFFFF; }
        for (int t = tid; t < 256; t += 32)
            #pragma unroll
            for (int r=0;r<4;r++) ins4(sv[t*4+r], si[t*4+r], mv, mi);
        #pragma unroll
        for (int r=0;r<4;r++){ sv[tid*4+r]=mv[r]; si[tid*4+r]=mi[r]; }
    }
    __syncthreads();
    // level 2: thread 0 merges 32 lane-lists (128 entries)
    if (tid == 0) {
        float tv[4]; int ti[4];
        #pragma unroll
        for (int r=0;r<4;r++){ tv[r]=-1e30f; ti[r]=0x7FFFFFFF; }
        for (int e=0;e<128;e++) ins4(sv[e], si[e], tv, ti);
        // sort indices ascending
        #pragma unroll
        for (int a=0;a<4;a++)
            #pragma unroll
            for (int c2=a+1;c2<4;c2++)
                if (ti[c2] < ti[a]) { int t=ti[a]; ti[a]=ti[c2]; ti[c2]=t; }
        #pragma unroll
        for (int r=0;r<4;r++) { g_topk[b*4+r] = ti[r]; tk[r] = ti[r]; }
    }
    __syncthreads();

    // imp_kept for this batch
    for (int j = tid; j < KEEP; j += 256) {
        int idx = (j < 4) ? tk[j] : (CAND + (j-4));
        out[OFF_IMP + b*KEEP + j] = g_imp[b*KV + idx];
    }

    // gather top-4 K/V rows for all 32 heads: 32h x 4slot x 32lane float4 tasks
    for (int t = tid; t < 4096; t += 256) {
        int h    = t >> 7;
        int r    = (t >> 5) & 3;
        int lane = t & 31;
        int bh   = b*Hh + h;
        int idx  = tk[r];
        size_t soff = ((size_t)bh*Ss + idx)*32 + lane;
        size_t doff = ((size_t)bh*KEEP + r)*32 + lane;
        ((float4*)(out + OFF_K))[doff] = ((const float4*)Kc)[soff];
        ((float4*)(out + OFF_V))[doff] = ((const float4*)Vc)[soff];
    }
}

// ---------------- 8. output projection: attn_out = ctx @ Wo ----------------
__global__ void k_oproj(const float* __restrict__ Wo, float* __restrict__ out) {
    __shared__ float h_sm[Bb*KC];
    int i0 = blockIdx.y * KC;
    int j  = blockIdx.x * 512 + threadIdx.x * 4;
    for (int idx = threadIdx.x; idx < Bb*KC; idx += blockDim.x)
        h_sm[idx] = g_ctx[(idx/KC)*Dd + i0 + (idx%KC)];
    __syncthreads();
    float4 acc[Bb];
    #pragma unroll
    for (int b=0;b<Bb;b++) acc[b] = make_float4(0.f,0.f,0.f,0.f);
    const float4* Wp = (const float4*)(Wo + (size_t)i0*Dd + j);
    for (int ii=0; ii<KC; ii+=4) {
        float4 w0 = __ldcs(&Wp[(size_t)(ii+0)*(Dd/4)]);
        float4 w1 = __ldcs(&Wp[(size_t)(ii+1)*(Dd/4)]);
        float4 w2 = __ldcs(&Wp[(size_t)(ii+2)*(Dd/4)]);
        float4 w3 = __ldcs(&Wp[(size_t)(ii+3)*(Dd/4)]);
        #pragma unroll
        for (int b=0;b<Bb;b++) {
            float h0 = h_sm[b*KC+ii+0], h1 = h_sm[b*KC+ii+1];
            float h2 = h_sm[b*KC+ii+2], h3 = h_sm[b*KC+ii+3];
            acc[b].x += h0*w0.x + h1*w1.x + h2*w2.x + h3*w3.x;
            acc[b].y += h0*w0.y + h1*w1.y + h2*w2.y + h3*w3.y;
            acc[b].z += h0*w0.z + h1*w1.z + h2*w2.z + h3*w3.z;
            acc[b].w += h0*w0.w + h1*w1.w + h2*w2.w + h3*w3.w;
        }
    }
    #pragma unroll
    for (int b=0;b<Bb;b++) {
        atomicAdd(&out[b*Dd+j  ], acc[b].x);
        atomicAdd(&out[b*Dd+j+1], acc[b].y);
        atomicAdd(&out[b*Dd+j+2], acc[b].z);
        atomicAdd(&out[b*Dd+j+3], acc[b].w);
    }
}

// ---------------- launch ----------------
extern "C" void kernel_launch(void* const* d_in, const int* in_sizes, int n_in,
                              void* d_out, int out_size) {
    const float* hs   = (const float*)d_in[0];
    const float* pk   = (const float*)d_in[1];
    const float* pv   = (const float*)d_in[2];
    const float* Wq   = (const float*)d_in[3];
    const float* Wk   = (const float*)d_in[4];
    const float* Wv   = (const float*)d_in[5];
    const float* Wo   = (const float*)d_in[6];
    const float* prev = (const float*)d_in[7];
    float* out = (float*)d_out;

    k_zero   <<<(Bb*Dd + 255)/256, 256>>>(out);
    k_proj   <<<dim3(Dd/512, Dd/KC, 3), 128>>>(hs, Wq, Wk, Wv);
    k_rope   <<<Bb*Hh, HD>>>();
    k_fused  <<<dim3(8, Bb*Hh), 256>>>(pk, pv, out);
    k_comb   <<<Bb*Hh, 128>>>(out);
    k_imp    <<<(Bb*KV + 255)/256, 256>>>(prev);
    k_topk   <<<Bb, 256>>>(pk, pv, out);
    k_oproj  <<<dim3(Dd/512, Dd/KC), 128>>>(Wo, out);
}